// round 2
// baseline (speedup 1.0000x reference)
#include <cuda_runtime.h>
#include <cstddef>

#define NN 100000
#define EE 1600000

// ---------------- device scratch (static allocation only) ----------------
__device__ float  g_h  [(size_t)NN * 64];   // per-layer transformed features
__device__ float  g_x1 [(size_t)NN * 64];   // layer-1 output, later JK-max in place
__device__ float2 g_asrc[NN];
__device__ float2 g_adst[NN];
__device__ int    g_deg [NN];
__device__ int    g_rowptr[NN + 1];
__device__ int    g_cursor[NN];
__device__ int    g_bsum[256];
__device__ int    g_csrc[EE];

// ---------------- CSR build ----------------
__global__ void k_zero_deg() {
    int i = blockIdx.x * blockDim.x + threadIdx.x;
    if (i < NN) g_deg[i] = 0;
}

__global__ void k_hist(const int* __restrict__ ei) {
    int e = blockIdx.x * blockDim.x + threadIdx.x;
    if (e < EE) atomicAdd(&g_deg[ei[EE + e]], 1);
}

__device__ __forceinline__ int blockScanEx(int v, int* ws, int nthreads) {
    int t = threadIdx.x;
    int lane = t & 31, wid = t >> 5;
    int x = v;
#pragma unroll
    for (int o = 1; o < 32; o <<= 1) {
        int y = __shfl_up_sync(0xffffffffu, x, o);
        if (lane >= o) x += y;
    }
    if (lane == 31) ws[wid] = x;
    __syncthreads();
    int nw = nthreads >> 5;
    if (wid == 0) {
        int s = (lane < nw) ? ws[lane] : 0;
#pragma unroll
        for (int o = 1; o < 32; o <<= 1) {
            int y = __shfl_up_sync(0xffffffffu, s, o);
            if (lane >= o) s += y;
        }
        if (lane < nw) ws[lane] = s;
    }
    __syncthreads();
    int off = (wid == 0) ? 0 : ws[wid - 1];
    return off + x - v;   // exclusive prefix
}

__global__ void k_scanA() {
    __shared__ int ws[32];
    int t = threadIdx.x;
    int i = blockIdx.x * 512 + t;
    int v = (i < NN) ? g_deg[i] : 0;
    int ex = blockScanEx(v, ws, 512);
    if (i < NN) g_rowptr[i] = ex;
    if (t == 511) g_bsum[blockIdx.x] = ex + v;
}

__global__ void k_scanB(int nb) {
    __shared__ int ws[32];
    int t = threadIdx.x;
    int v = (t < nb) ? g_bsum[t] : 0;
    int ex = blockScanEx(v, ws, 256);
    if (t < nb) g_bsum[t] = ex;
}

__global__ void k_scanC() {
    int i = blockIdx.x * 512 + threadIdx.x;
    if (i < NN) {
        int val = g_rowptr[i] + g_bsum[blockIdx.x];
        g_rowptr[i] = val;
        g_cursor[i] = val;
    }
    if (i == 0) g_rowptr[NN] = EE;
}

__global__ void k_fill(const int* __restrict__ ei) {
    int e = blockIdx.x * blockDim.x + threadIdx.x;
    if (e < EE) {
        int s = ei[e];
        int d = ei[EE + e];
        int p = atomicAdd(&g_cursor[d], 1);
        g_csrc[p] = s;
    }
}

// ---------------- dense GEMM: Y[N,COUT] = X[N,FIN] @ W[FIN,COUT] (+bias) ----------------
template <int FIN, int COUT, int RG, int CG>
__global__ void k_gemm(const float* __restrict__ X, const float* __restrict__ W,
                       const float* __restrict__ bias, float* __restrict__ Y) {
    constexpr int ROWS = RG * 4;
    constexpr int KC = 32;
    constexpr int NT = RG * CG;
    __shared__ __align__(16) float sX[KC][ROWS + 4];   // transposed: sX[k][r]
    __shared__ __align__(16) float sW[KC][COUT];

    int t = threadIdx.x;
    int rg = t % RG, cg = t / RG;
    int row0 = blockIdx.x * ROWS;
    float acc[4][4] = {};

    for (int kc = 0; kc < FIN; kc += KC) {
        for (int idx = t; idx < ROWS * KC; idx += NT) {
            int r = idx >> 5, k = idx & 31;       // KC == 32
            int gr = row0 + r;
            sX[k][r] = (gr < NN) ? X[(size_t)gr * FIN + kc + k] : 0.f;
        }
        for (int idx = t; idx < KC * COUT; idx += NT) {
            int k = idx / COUT, c = idx % COUT;
            sW[k][c] = W[(size_t)(kc + k) * COUT + c];
        }
        __syncthreads();
#pragma unroll
        for (int k = 0; k < KC; k++) {
            float4 xv = *(const float4*)&sX[k][rg * 4];
            float4 wv = *(const float4*)&sW[k][cg * 4];
            acc[0][0] += xv.x * wv.x; acc[0][1] += xv.x * wv.y; acc[0][2] += xv.x * wv.z; acc[0][3] += xv.x * wv.w;
            acc[1][0] += xv.y * wv.x; acc[1][1] += xv.y * wv.y; acc[1][2] += xv.y * wv.z; acc[1][3] += xv.y * wv.w;
            acc[2][0] += xv.z * wv.x; acc[2][1] += xv.z * wv.y; acc[2][2] += xv.z * wv.z; acc[2][3] += xv.z * wv.w;
            acc[3][0] += xv.w * wv.x; acc[3][1] += xv.w * wv.y; acc[3][2] += xv.w * wv.z; acc[3][3] += xv.w * wv.w;
        }
        __syncthreads();
    }

    float b0 = 0.f, b1 = 0.f, b2 = 0.f, b3 = 0.f;
    if (bias) { b0 = bias[cg * 4]; b1 = bias[cg * 4 + 1]; b2 = bias[cg * 4 + 2]; b3 = bias[cg * 4 + 3]; }
#pragma unroll
    for (int i = 0; i < 4; i++) {
        int gr = row0 + rg * 4 + i;
        if (gr < NN) {
            float4 o;
            o.x = acc[i][0] + b0; o.y = acc[i][1] + b1;
            o.z = acc[i][2] + b2; o.w = acc[i][3] + b3;
            *(float4*)&Y[(size_t)gr * COUT + cg * 4] = o;
        }
    }
}

// ---------------- attention logits per node ----------------
__global__ void k_alphas(const float* __restrict__ a_s, const float* __restrict__ a_d) {
    int w = (blockIdx.x * blockDim.x + threadIdx.x) >> 5;
    if (w >= NN) return;
    int lane = threadIdx.x & 31;
    const float* hr = g_h + (size_t)w * 64;
    float h0 = hr[lane], h1 = hr[32 + lane];
    float s0 = h0 * a_s[lane], s1 = h1 * a_s[32 + lane];
    float d0 = h0 * a_d[lane], d1 = h1 * a_d[32 + lane];
#pragma unroll
    for (int o = 16; o; o >>= 1) {
        s0 += __shfl_xor_sync(0xffffffffu, s0, o);
        s1 += __shfl_xor_sync(0xffffffffu, s1, o);
        d0 += __shfl_xor_sync(0xffffffffu, d0, o);
        d1 += __shfl_xor_sync(0xffffffffu, d1, o);
    }
    if (lane == 0) {
        g_asrc[w] = make_float2(s0, s1);
        g_adst[w] = make_float2(d0, d1);
    }
}

__device__ __forceinline__ float lrelu(float x) { return x > 0.f ? x : 0.2f * x; }

// ---------------- softmax aggregation, one warp per destination node ----------------
// LAYER==1: out = ELU(BN(agg + b1)) -> g_x1
// LAYER==2: g_x1 = max(g_x1, agg + b2)   (JK max fused, in place)
template <int LAYER>
__global__ void k_agg(const float* __restrict__ bias,
                      const float* __restrict__ bgamma, const float* __restrict__ bbeta,
                      const float* __restrict__ bmean,  const float* __restrict__ bvar) {
    int w = (blockIdx.x * blockDim.x + threadIdx.x) >> 5;
    if (w >= NN) return;
    int lane = threadIdx.x & 31;

    float2 ad = g_adst[w];
    float2 asn = g_asrc[w];
    int s0 = g_rowptr[w], s1 = g_rowptr[w + 1];

    // phase 1: softmax denominators (no max shift needed: logits bounded)
    float dd0 = 0.f, dd1 = 0.f;
    for (int i = s0 + lane; i < s1; i += 32) {
        int s = g_csrc[i];
        float2 a = g_asrc[s];
        dd0 += __expf(lrelu(a.x + ad.x));
        dd1 += __expf(lrelu(a.y + ad.y));
    }
    if (lane == 0) {   // self loop
        dd0 += __expf(lrelu(asn.x + ad.x));
        dd1 += __expf(lrelu(asn.y + ad.y));
    }
#pragma unroll
    for (int o = 16; o; o >>= 1) {
        dd0 += __shfl_xor_sync(0xffffffffu, dd0, o);
        dd1 += __shfl_xor_sync(0xffffffffu, dd1, o);
    }
    float inv0 = 1.f / (dd0 + 1e-16f);
    float inv1 = 1.f / (dd1 + 1e-16f);

    // phase 2: weighted gather of h[src]; lane c handles channels c and 32+c
    float acc0 = 0.f, acc1 = 0.f;
    for (int i = s0; i < s1; i++) {
        int s = g_csrc[i];                 // broadcast load (all lanes same addr)
        float2 a = g_asrc[s];
        float w0 = __expf(lrelu(a.x + ad.x)) * inv0;
        float w1 = __expf(lrelu(a.y + ad.y)) * inv1;
        const float* hr = g_h + (size_t)s * 64;
        acc0 += w0 * hr[lane];
        acc1 += w1 * hr[32 + lane];
    }
    {   // self loop
        float w0 = __expf(lrelu(asn.x + ad.x)) * inv0;
        float w1 = __expf(lrelu(asn.y + ad.y)) * inv1;
        const float* hr = g_h + (size_t)w * 64;
        acc0 += w0 * hr[lane];
        acc1 += w1 * hr[32 + lane];
    }

    int c0 = lane, c1 = 32 + lane;
    float o0 = acc0 + bias[c0];
    float o1 = acc1 + bias[c1];

    if (LAYER == 1) {
        float sc0 = bgamma[c0] * rsqrtf(bvar[c0] + 1e-5f);
        float sc1 = bgamma[c1] * rsqrtf(bvar[c1] + 1e-5f);
        float y0 = (o0 - bmean[c0]) * sc0 + bbeta[c0];
        float y1 = (o1 - bmean[c1]) * sc1 + bbeta[c1];
        y0 = y0 > 0.f ? y0 : expm1f(y0);
        y1 = y1 > 0.f ? y1 : expm1f(y1);
        g_x1[(size_t)w * 64 + c0] = y0;
        g_x1[(size_t)w * 64 + c1] = y1;
    } else {
        float* p = &g_x1[(size_t)w * 64];
        p[c0] = fmaxf(p[c0], o0);
        p[c1] = fmaxf(p[c1], o1);
    }
}

// ---------------- launch ----------------
extern "C" void kernel_launch(void* const* d_in, const int* in_sizes, int n_in,
                              void* d_out, int out_size) {
    const float* node_feat = (const float*)d_in[0];
    const int*   ei        = (const int*)  d_in[1];
    const float* W1        = (const float*)d_in[2];
    const float* as1       = (const float*)d_in[3];
    const float* ad1       = (const float*)d_in[4];
    const float* b1        = (const float*)d_in[5];
    const float* bng       = (const float*)d_in[6];
    const float* bnb       = (const float*)d_in[7];
    const float* bnm       = (const float*)d_in[8];
    const float* bnv       = (const float*)d_in[9];
    const float* W2        = (const float*)d_in[10];
    const float* as2       = (const float*)d_in[11];
    const float* ad2       = (const float*)d_in[12];
    const float* b2        = (const float*)d_in[13];
    const float* Wf        = (const float*)d_in[14];
    const float* bf        = (const float*)d_in[15];
    float* out = (float*)d_out;

    float *ph = nullptr, *px1 = nullptr;
    cudaGetSymbolAddress((void**)&ph, g_h);
    cudaGetSymbolAddress((void**)&px1, g_x1);

    const int eb = (EE + 255) / 256;
    const int nb = (NN + 511) / 512;   // 196 scan blocks
    const int ab = (NN + 7) / 8;       // warp-per-node kernels, 8 warps/block
    const int gb = (NN + 63) / 64;     // gemm blocks

    // CSR build (reused by both layers)
    k_zero_deg<<<(NN + 255) / 256, 256>>>();
    k_hist<<<eb, 256>>>(ei);
    k_scanA<<<nb, 512>>>();
    k_scanB<<<1, 256>>>(nb);
    k_scanC<<<nb, 512>>>();
    k_fill<<<eb, 256>>>(ei);

    // Layer 1
    k_gemm<128, 64, 16, 16><<<gb, 256>>>(node_feat, W1, nullptr, ph);
    k_alphas<<<ab, 256>>>(as1, ad1);
    k_agg<1><<<ab, 256>>>(b1, bng, bnb, bnm, bnv);

    // Layer 2
    k_gemm<64, 64, 16, 16><<<gb, 256>>>(px1, W2, nullptr, ph);
    k_alphas<<<ab, 256>>>(as2, ad2);
    k_agg<2><<<ab, 256>>>(b2, nullptr, nullptr, nullptr, nullptr);

    // Final projection on JK-max output
    k_gemm<64, 40, 16, 10><<<gb, 160>>>(px1, Wf, bf, out);
}

// round 3
// speedup vs baseline: 1.2681x; 1.2681x over previous
#include <cuda_runtime.h>
#include <cstddef>

#define NN 100000
#define EE 1600000

// ---------------- device scratch (static allocation only) ----------------
__device__ float  g_h  [(size_t)NN * 64];   // per-layer transformed features
__device__ float  g_x1 [(size_t)NN * 64];   // layer-1 output, later JK-max in place
__device__ float2 g_asrc[NN];
__device__ float2 g_adst[NN];
__device__ int    g_deg [NN];
__device__ int    g_rowptr[NN + 1];
__device__ int    g_cursor[NN];
__device__ int    g_bsum[256];
__device__ int    g_csrc[EE];

// ---------------- CSR build ----------------
__global__ void k_zero_deg() {
    int i = blockIdx.x * blockDim.x + threadIdx.x;
    if (i < NN) g_deg[i] = 0;
}

__global__ void k_hist(const int* __restrict__ ei) {
    int e = blockIdx.x * blockDim.x + threadIdx.x;
    if (e < EE) atomicAdd(&g_deg[ei[EE + e]], 1);
}

__device__ __forceinline__ int blockScanEx(int v, int* ws, int nthreads) {
    int t = threadIdx.x;
    int lane = t & 31, wid = t >> 5;
    int x = v;
#pragma unroll
    for (int o = 1; o < 32; o <<= 1) {
        int y = __shfl_up_sync(0xffffffffu, x, o);
        if (lane >= o) x += y;
    }
    if (lane == 31) ws[wid] = x;
    __syncthreads();
    int nw = nthreads >> 5;
    if (wid == 0) {
        int s = (lane < nw) ? ws[lane] : 0;
#pragma unroll
        for (int o = 1; o < 32; o <<= 1) {
            int y = __shfl_up_sync(0xffffffffu, s, o);
            if (lane >= o) s += y;
        }
        if (lane < nw) ws[lane] = s;
    }
    __syncthreads();
    int off = (wid == 0) ? 0 : ws[wid - 1];
    return off + x - v;   // exclusive prefix
}

__global__ void k_scanA() {
    __shared__ int ws[32];
    int t = threadIdx.x;
    int i = blockIdx.x * 512 + t;
    int v = (i < NN) ? g_deg[i] : 0;
    int ex = blockScanEx(v, ws, 512);
    if (i < NN) g_rowptr[i] = ex;
    if (t == 511) g_bsum[blockIdx.x] = ex + v;
}

__global__ void k_scanB(int nb) {
    __shared__ int ws[32];
    int t = threadIdx.x;
    int v = (t < nb) ? g_bsum[t] : 0;
    int ex = blockScanEx(v, ws, 256);
    if (t < nb) g_bsum[t] = ex;
}

__global__ void k_scanC() {
    int i = blockIdx.x * 512 + threadIdx.x;
    if (i < NN) {
        int val = g_rowptr[i] + g_bsum[blockIdx.x];
        g_rowptr[i] = val;
        g_cursor[i] = val;
    }
    if (i == 0) g_rowptr[NN] = EE;
}

__global__ void k_fill(const int* __restrict__ ei) {
    int e = blockIdx.x * blockDim.x + threadIdx.x;
    if (e < EE) {
        int s = ei[e];
        int d = ei[EE + e];
        int p = atomicAdd(&g_cursor[d], 1);
        g_csrc[p] = s;
    }
}

// ---------------- dense GEMM: Y[N,COUT] = X[N,FIN] @ W[FIN,COUT] (+bias) ----------
// Tile 64 rows x COUT cols, thread = 4x4. rg = t/CG (row group), cg = t%CG.
// If ALPHA: fused attention-logit epilogue writes g_asrc/g_adst (requires CG==16).
template <int FIN, int COUT, int CG, bool ALPHA>
__global__ void k_gemm(const float* __restrict__ X, const float* __restrict__ W,
                       const float* __restrict__ bias, float* __restrict__ Y,
                       const float* __restrict__ a_s, const float* __restrict__ a_d) {
    constexpr int RG = 16;
    constexpr int ROWS = RG * 4;            // 64
    constexpr int KC = 32;
    constexpr int NT = RG * CG;
    __shared__ __align__(16) float sX[KC][ROWS + 4];   // transposed: sX[k][r]
    __shared__ __align__(16) float sW[KC][COUT];

    int t = threadIdx.x;
    int rg = t / CG, cg = t % CG;           // warp (CG=16): rg = 2w + lane/16, cg = lane%16
    int row0 = blockIdx.x * ROWS;
    float acc[4][4] = {};

    for (int kc = 0; kc < FIN; kc += KC) {
        for (int idx = t; idx < ROWS * KC; idx += NT) {
            int r = idx >> 5, k = idx & 31;       // KC == 32
            int gr = row0 + r;
            sX[k][r] = (gr < NN) ? X[(size_t)gr * FIN + kc + k] : 0.f;
        }
        for (int idx = t; idx < KC * COUT; idx += NT) {
            int k = idx / COUT, c = idx % COUT;
            sW[k][c] = W[(size_t)(kc + k) * COUT + c];
        }
        __syncthreads();
#pragma unroll
        for (int k = 0; k < KC; k++) {
            float4 xv = *(const float4*)&sX[k][rg * 4];
            float4 wv = *(const float4*)&sW[k][cg * 4];
            acc[0][0] += xv.x * wv.x; acc[0][1] += xv.x * wv.y; acc[0][2] += xv.x * wv.z; acc[0][3] += xv.x * wv.w;
            acc[1][0] += xv.y * wv.x; acc[1][1] += xv.y * wv.y; acc[1][2] += xv.y * wv.z; acc[1][3] += xv.y * wv.w;
            acc[2][0] += xv.z * wv.x; acc[2][1] += xv.z * wv.y; acc[2][2] += xv.z * wv.z; acc[2][3] += xv.z * wv.w;
            acc[3][0] += xv.w * wv.x; acc[3][1] += xv.w * wv.y; acc[3][2] += xv.w * wv.z; acc[3][3] += xv.w * wv.w;
        }
        __syncthreads();
    }

    float b0 = 0.f, b1 = 0.f, b2 = 0.f, b3 = 0.f;
    if (bias) { b0 = bias[cg * 4]; b1 = bias[cg * 4 + 1]; b2 = bias[cg * 4 + 2]; b3 = bias[cg * 4 + 3]; }
#pragma unroll
    for (int i = 0; i < 4; i++) {
        int gr = row0 + rg * 4 + i;
        if (gr < NN) {
            float4 o;
            o.x = acc[i][0] + b0; o.y = acc[i][1] + b1;
            o.z = acc[i][2] + b2; o.w = acc[i][3] + b3;
            *(float4*)&Y[(size_t)gr * COUT + cg * 4] = o;
        }
    }

    if (ALPHA) {
        // per-thread partial dots over its 4 cols, reduce across the 8 cg-lanes of each head
        float as4[4], ad4[4];
#pragma unroll
        for (int j = 0; j < 4; j++) { as4[j] = a_s[cg * 4 + j]; ad4[j] = a_d[cg * 4 + j]; }
#pragma unroll
        for (int i = 0; i < 4; i++) {
            float ps = 0.f, pd = 0.f;
#pragma unroll
            for (int j = 0; j < 4; j++) { ps += acc[i][j] * as4[j]; pd += acc[i][j] * ad4[j]; }
#pragma unroll
            for (int o = 4; o; o >>= 1) {
                ps += __shfl_xor_sync(0xffffffffu, ps, o);
                pd += __shfl_xor_sync(0xffffffffu, pd, o);
            }
            // 8-lane groups now hold per-head sums; xor 8 swaps head partners
            float ps1 = __shfl_xor_sync(0xffffffffu, ps, 8);
            float pd1 = __shfl_xor_sync(0xffffffffu, pd, 8);
            if (cg == 0) {
                int gr = row0 + rg * 4 + i;
                if (gr < NN) {
                    g_asrc[gr] = make_float2(ps, ps1);
                    g_adst[gr] = make_float2(pd, pd1);
                }
            }
        }
    }
}

__device__ __forceinline__ float lrelu(float x) { return x > 0.f ? x : 0.2f * x; }

// ---------------- single-pass softmax aggregation, one warp per destination ------
// out = (sum_j e_j * h_j) / (sum_j e_j)  — normalization deferred to the end.
// Lane L owns channels 2L, 2L+1 (head = L<16).
// LAYER==1: out = ELU(BN(agg + b1)) -> g_x1
// LAYER==2: g_x1 = max(g_x1, agg + b2)   (JK max fused, in place)
template <int LAYER>
__global__ void k_agg(const float* __restrict__ bias,
                      const float* __restrict__ bgamma, const float* __restrict__ bbeta,
                      const float* __restrict__ bmean,  const float* __restrict__ bvar) {
    int w = (blockIdx.x * blockDim.x + threadIdx.x) >> 5;
    if (w >= NN) return;
    int lane = threadIdx.x & 31;

    float2 ad = g_adst[w];
    int s0 = g_rowptr[w], s1 = g_rowptr[w + 1];

    float accx = 0.f, accy = 0.f;
    float dd0 = 0.f, dd1 = 0.f;

    for (int base = s0; base < s1; base += 32) {
        int n = s1 - base; if (n > 32) n = 32;
        int s = 0; float w0 = 0.f, w1 = 0.f;
        if (lane < n) {
            s = g_csrc[base + lane];                  // coalesced
            float2 a = g_asrc[s];                     // parallel gather
            w0 = __expf(lrelu(a.x + ad.x));
            w1 = __expf(lrelu(a.y + ad.y));
        }
        dd0 += w0; dd1 += w1;
        for (int k = 0; k < n; k++) {
            int   ss  = __shfl_sync(0xffffffffu, s,  k);
            float ww0 = __shfl_sync(0xffffffffu, w0, k);
            float ww1 = __shfl_sync(0xffffffffu, w1, k);
            float2 hv = *(const float2*)(g_h + (size_t)ss * 64 + 2 * lane);
            float ww = (lane < 16) ? ww0 : ww1;
            accx += ww * hv.x; accy += ww * hv.y;
        }
    }

    // self loop + lane reduction of denominators
    {
        float2 asn = g_asrc[w];
        float w0 = __expf(lrelu(asn.x + ad.x));
        float w1 = __expf(lrelu(asn.y + ad.y));
        float2 hv = *(const float2*)(g_h + (size_t)w * 64 + 2 * lane);
        float ww = (lane < 16) ? w0 : w1;
        accx += ww * hv.x; accy += ww * hv.y;
#pragma unroll
        for (int o = 16; o; o >>= 1) {
            dd0 += __shfl_xor_sync(0xffffffffu, dd0, o);
            dd1 += __shfl_xor_sync(0xffffffffu, dd1, o);
        }
        dd0 += w0; dd1 += w1;
    }

    float inv = (lane < 16) ? (1.f / (dd0 + 1e-16f)) : (1.f / (dd1 + 1e-16f));
    int c0 = 2 * lane, c1 = c0 + 1;
    float o0 = accx * inv + bias[c0];
    float o1 = accy * inv + bias[c1];

    if (LAYER == 1) {
        float sc0 = bgamma[c0] * rsqrtf(bvar[c0] + 1e-5f);
        float sc1 = bgamma[c1] * rsqrtf(bvar[c1] + 1e-5f);
        float y0 = (o0 - bmean[c0]) * sc0 + bbeta[c0];
        float y1 = (o1 - bmean[c1]) * sc1 + bbeta[c1];
        y0 = y0 > 0.f ? y0 : expm1f(y0);
        y1 = y1 > 0.f ? y1 : expm1f(y1);
        *(float2*)(g_x1 + (size_t)w * 64 + c0) = make_float2(y0, y1);
    } else {
        float2* p = (float2*)(g_x1 + (size_t)w * 64 + c0);
        float2 v = *p;
        v.x = fmaxf(v.x, o0);
        v.y = fmaxf(v.y, o1);
        *p = v;
    }
}

// ---------------- launch ----------------
extern "C" void kernel_launch(void* const* d_in, const int* in_sizes, int n_in,
                              void* d_out, int out_size) {
    const float* node_feat = (const float*)d_in[0];
    const int*   ei        = (const int*)  d_in[1];
    const float* W1        = (const float*)d_in[2];
    const float* as1       = (const float*)d_in[3];
    const float* ad1       = (const float*)d_in[4];
    const float* b1        = (const float*)d_in[5];
    const float* bng       = (const float*)d_in[6];
    const float* bnb       = (const float*)d_in[7];
    const float* bnm       = (const float*)d_in[8];
    const float* bnv       = (const float*)d_in[9];
    const float* W2        = (const float*)d_in[10];
    const float* as2       = (const float*)d_in[11];
    const float* ad2       = (const float*)d_in[12];
    const float* b2        = (const float*)d_in[13];
    const float* Wf        = (const float*)d_in[14];
    const float* bf        = (const float*)d_in[15];
    float* out = (float*)d_out;

    float *ph = nullptr, *px1 = nullptr;
    cudaGetSymbolAddress((void**)&ph, g_h);
    cudaGetSymbolAddress((void**)&px1, g_x1);

    const int eb = (EE + 255) / 256;
    const int nb = (NN + 511) / 512;   // 196 scan blocks
    const int ab = (NN + 7) / 8;       // warp-per-node kernels, 8 warps/block
    const int gb = (NN + 63) / 64;     // gemm blocks

    // CSR build (reused by both layers)
    k_zero_deg<<<(NN + 255) / 256, 256>>>();
    k_hist<<<eb, 256>>>(ei);
    k_scanA<<<nb, 512>>>();
    k_scanB<<<1, 256>>>(nb);
    k_scanC<<<nb, 512>>>();
    k_fill<<<eb, 256>>>(ei);

    // Layer 1: GEMM + fused alphas, then single-pass softmax aggregation
    k_gemm<128, 64, 16, true><<<gb, 256>>>(node_feat, W1, nullptr, ph, as1, ad1);
    k_agg<1><<<ab, 256>>>(b1, bng, bnb, bnm, bnv);

    // Layer 2
    k_gemm<64, 64, 16, true><<<gb, 256>>>(px1, W2, nullptr, ph, as2, ad2);
    k_agg<2><<<ab, 256>>>(b2, nullptr, nullptr, nullptr, nullptr);

    // Final projection on JK-max output
    k_gemm<64, 40, 10, false><<<gb, 160>>>(px1, Wf, bf, out, nullptr, nullptr);
}

// round 6
// speedup vs baseline: 1.4052x; 1.1081x over previous
#include <cuda_runtime.h>
#include <cstddef>

#define NN 100000
#define EE 1600000

// ---------------- device scratch (static allocation only) ----------------
__device__ float  g_h  [(size_t)NN * 64];   // per-layer transformed features
__device__ float  g_x1 [(size_t)NN * 64];   // layer-1 output, later JK-max in place
__device__ float2 g_asrc[NN];
__device__ float2 g_adst[NN];
__device__ int    g_deg [NN];
__device__ int    g_rowptr[NN + 1];
__device__ int    g_cursor[NN];
__device__ int    g_bsum[256];
__device__ int    g_csrc[EE];

// ---------------- CSR build ----------------
__global__ void k_hist(const int* __restrict__ ei) {
    int e4 = blockIdx.x * blockDim.x + threadIdx.x;
    if (e4 < EE / 4) {
        int4 d = ((const int4*)(ei + EE))[e4];
        atomicAdd(&g_deg[d.x], 1);
        atomicAdd(&g_deg[d.y], 1);
        atomicAdd(&g_deg[d.z], 1);
        atomicAdd(&g_deg[d.w], 1);
    }
}

__device__ __forceinline__ int blockScanEx(int v, int* ws, int nthreads) {
    int t = threadIdx.x;
    int lane = t & 31, wid = t >> 5;
    int x = v;
#pragma unroll
    for (int o = 1; o < 32; o <<= 1) {
        int y = __shfl_up_sync(0xffffffffu, x, o);
        if (lane >= o) x += y;
    }
    if (lane == 31) ws[wid] = x;
    __syncthreads();
    int nw = nthreads >> 5;
    if (wid == 0) {
        int s = (lane < nw) ? ws[lane] : 0;
#pragma unroll
        for (int o = 1; o < 32; o <<= 1) {
            int y = __shfl_up_sync(0xffffffffu, s, o);
            if (lane >= o) s += y;
        }
        if (lane < nw) ws[lane] = s;
    }
    __syncthreads();
    int off = (wid == 0) ? 0 : ws[wid - 1];
    return off + x - v;   // exclusive prefix
}

__global__ void k_scanA() {
    __shared__ int ws[32];
    int t = threadIdx.x;
    int i = blockIdx.x * 512 + t;
    int v = (i < NN) ? g_deg[i] : 0;
    int ex = blockScanEx(v, ws, 512);
    if (i < NN) g_rowptr[i] = ex;
    if (t == 511) g_bsum[blockIdx.x] = ex + v;
}

__global__ void k_scanB(int nb) {
    __shared__ int ws[32];
    int t = threadIdx.x;
    int v = (t < nb) ? g_bsum[t] : 0;
    int ex = blockScanEx(v, ws, 256);
    if (t < nb) g_bsum[t] = ex;
}

__global__ void k_scanC() {
    int i = blockIdx.x * 512 + threadIdx.x;
    if (i < NN) {
        int val = g_rowptr[i] + g_bsum[blockIdx.x];
        g_rowptr[i] = val;
        g_cursor[i] = val;
    }
    if (i == 0) g_rowptr[NN] = EE;
}

__global__ void k_fill(const int* __restrict__ ei) {
    int e4 = blockIdx.x * blockDim.x + threadIdx.x;
    if (e4 < EE / 4) {
        int4 s = ((const int4*)ei)[e4];
        int4 d = ((const int4*)(ei + EE))[e4];
        g_csrc[atomicAdd(&g_cursor[d.x], 1)] = s.x;
        g_csrc[atomicAdd(&g_cursor[d.y], 1)] = s.y;
        g_csrc[atomicAdd(&g_cursor[d.z], 1)] = s.z;
        g_csrc[atomicAdd(&g_cursor[d.w], 1)] = s.w;
    }
}

// ---------------- dense GEMM (8x4 register tile, COUT=64) --------------------
// 128 rows/block, 256 threads: rg = t/16 (8 rows each), cg = t%16 (4 cols each).
// ALPHA: fused attention-logit epilogue writes g_asrc/g_adst.
template <int FIN, bool ALPHA>
__global__ void k_gemm64(const float* __restrict__ X, const float* __restrict__ W,
                         float* __restrict__ Y,
                         const float* __restrict__ a_s, const float* __restrict__ a_d) {
    constexpr int COUT = 64;
    constexpr int ROWS = 128;
    constexpr int KC = 32;
    __shared__ __align__(16) float sX[KC][ROWS + 4];   // row stride 132 floats (16B mult)
    __shared__ __align__(16) float sW[KC][COUT];

    int t = threadIdx.x;
    int rg = t >> 4, cg = t & 15;
    int row0 = blockIdx.x * ROWS;
    float acc[8][4] = {};

    for (int kc = 0; kc < FIN; kc += KC) {
        // load X tile transposed: each thread loads float4 along k
#pragma unroll
        for (int it = 0; it < ROWS * KC / 4 / 256; it++) {
            int idx = t + it * 256;
            int r = idx >> 3, kq = idx & 7;
            int gr = row0 + r;
            float4 v = make_float4(0.f, 0.f, 0.f, 0.f);
            if (gr < NN) v = *(const float4*)&X[(size_t)gr * FIN + kc + kq * 4];
            sX[kq * 4 + 0][r] = v.x;
            sX[kq * 4 + 1][r] = v.y;
            sX[kq * 4 + 2][r] = v.z;
            sX[kq * 4 + 3][r] = v.w;
        }
#pragma unroll
        for (int it = 0; it < KC * COUT / 4 / 256; it++) {
            int idx = t + it * 256;
            int k = idx >> 4, cq = idx & 15;
            *(float4*)&sW[k][cq * 4] = *(const float4*)&W[(size_t)(kc + k) * COUT + cq * 4];
        }
        __syncthreads();
#pragma unroll
        for (int k = 0; k < KC; k++) {
            float4 xa = *(const float4*)&sX[k][rg * 8];
            float4 xb = *(const float4*)&sX[k][rg * 8 + 4];
            float4 wv = *(const float4*)&sW[k][cg * 4];
            float xr[8] = {xa.x, xa.y, xa.z, xa.w, xb.x, xb.y, xb.z, xb.w};
#pragma unroll
            for (int i = 0; i < 8; i++) {
                acc[i][0] += xr[i] * wv.x;
                acc[i][1] += xr[i] * wv.y;
                acc[i][2] += xr[i] * wv.z;
                acc[i][3] += xr[i] * wv.w;
            }
        }
        __syncthreads();
    }

#pragma unroll
    for (int i = 0; i < 8; i++) {
        int gr = row0 + rg * 8 + i;
        if (gr < NN)
            *(float4*)&Y[(size_t)gr * COUT + cg * 4] =
                make_float4(acc[i][0], acc[i][1], acc[i][2], acc[i][3]);
    }

    if (ALPHA) {
        float as4[4], ad4[4];
#pragma unroll
        for (int j = 0; j < 4; j++) { as4[j] = a_s[cg * 4 + j]; ad4[j] = a_d[cg * 4 + j]; }
#pragma unroll
        for (int i = 0; i < 8; i++) {
            float ps = 0.f, pd = 0.f;
#pragma unroll
            for (int j = 0; j < 4; j++) { ps += acc[i][j] * as4[j]; pd += acc[i][j] * ad4[j]; }
#pragma unroll
            for (int o = 4; o; o >>= 1) {
                ps += __shfl_xor_sync(0xffffffffu, ps, o);
                pd += __shfl_xor_sync(0xffffffffu, pd, o);
            }
            float ps1 = __shfl_xor_sync(0xffffffffu, ps, 8);
            float pd1 = __shfl_xor_sync(0xffffffffu, pd, 8);
            if (cg == 0) {
                int gr = row0 + rg * 8 + i;
                if (gr < NN) {
                    g_asrc[gr] = make_float2(ps, ps1);
                    g_adst[gr] = make_float2(pd, pd1);
                }
            }
        }
    }
}

// ---------------- final GEMM (4x4 tile, COUT=40) -----------------------------
__global__ void k_gemmf(const float* __restrict__ X, const float* __restrict__ W,
                        const float* __restrict__ bias, float* __restrict__ Y) {
    constexpr int FIN = 64, COUT = 40, RG = 16, CG = 10;
    constexpr int ROWS = RG * 4, KC = 32, NT = RG * CG;
    __shared__ __align__(16) float sX[KC][ROWS + 4];
    __shared__ __align__(16) float sW[KC][COUT];

    int t = threadIdx.x;
    int rg = t / CG, cg = t % CG;
    int row0 = blockIdx.x * ROWS;
    float acc[4][4] = {};

    for (int kc = 0; kc < FIN; kc += KC) {
        for (int idx = t; idx < ROWS * KC; idx += NT) {
            int r = idx >> 5, k = idx & 31;
            int gr = row0 + r;
            sX[k][r] = (gr < NN) ? X[(size_t)gr * FIN + kc + k] : 0.f;
        }
        for (int idx = t; idx < KC * COUT; idx += NT) {
            int k = idx / COUT, c = idx % COUT;
            sW[k][c] = W[(size_t)(kc + k) * COUT + c];
        }
        __syncthreads();
#pragma unroll
        for (int k = 0; k < KC; k++) {
            float4 xv = *(const float4*)&sX[k][rg * 4];
            float4 wv = *(const float4*)&sW[k][cg * 4];
            float xr[4] = {xv.x, xv.y, xv.z, xv.w};
#pragma unroll
            for (int i = 0; i < 4; i++) {
                acc[i][0] += xr[i] * wv.x;
                acc[i][1] += xr[i] * wv.y;
                acc[i][2] += xr[i] * wv.z;
                acc[i][3] += xr[i] * wv.w;
            }
        }
        __syncthreads();
    }

    float b0 = bias[cg * 4], b1 = bias[cg * 4 + 1], b2 = bias[cg * 4 + 2], b3 = bias[cg * 4 + 3];
#pragma unroll
    for (int i = 0; i < 4; i++) {
        int gr = row0 + rg * 4 + i;
        if (gr < NN) {
            float4 o;
            o.x = acc[i][0] + b0; o.y = acc[i][1] + b1;
            o.z = acc[i][2] + b2; o.w = acc[i][3] + b3;
            *(float4*)&Y[(size_t)gr * COUT + cg * 4] = o;
        }
    }
}

__device__ __forceinline__ float lrelu(float x) { return x > 0.f ? x : 0.2f * x; }

// ---------------- single-pass softmax aggregation, one warp per destination ------
// Batch of 32 edges staged in smem as (src, w_head) pairs; inner loop is
// one broadcast LDS.64 + one LDG.64 + 2 FMA per edge.
template <int LAYER>
__global__ void k_agg(const float* __restrict__ bias,
                      const float* __restrict__ bgamma, const float* __restrict__ bbeta,
                      const float* __restrict__ bmean,  const float* __restrict__ bvar) {
    __shared__ __align__(16) float2 buf[8][32][2];   // [warp][edge][half] = (srcbits, w_half)

    int w = (blockIdx.x * blockDim.x + threadIdx.x) >> 5;
    if (w >= NN) return;
    int lane = threadIdx.x & 31;
    int wid = threadIdx.x >> 5;
    int half = lane >> 4;

    float2 ad = g_adst[w];
    int s0 = g_rowptr[w], s1 = g_rowptr[w + 1];

    float accx = 0.f, accy = 0.f;
    float dd0 = 0.f, dd1 = 0.f;

    for (int base = s0; base < s1; base += 32) {
        int n = s1 - base; if (n > 32) n = 32;
        if (lane < n) {
            int s = g_csrc[base + lane];                  // coalesced
            float2 a = g_asrc[s];                         // parallel gather
            float w0 = __expf(lrelu(a.x + ad.x));
            float w1 = __expf(lrelu(a.y + ad.y));
            dd0 += w0; dd1 += w1;
            float sb = __int_as_float(s);
            buf[wid][lane][0] = make_float2(sb, w0);
            buf[wid][lane][1] = make_float2(sb, w1);
        }
        __syncwarp();
#pragma unroll 2
        for (int k = 0; k < n; k++) {
            float2 e = buf[wid][k][half];                 // broadcast LDS.64
            int ss = __float_as_int(e.x);
            float2 hv = *(const float2*)(g_h + (size_t)ss * 64 + 2 * lane);
            accx += e.y * hv.x;
            accy += e.y * hv.y;
        }
        __syncwarp();
    }

    // self loop + lane reduction of denominators
    {
        float2 asn = g_asrc[w];
        float w0 = __expf(lrelu(asn.x + ad.x));
        float w1 = __expf(lrelu(asn.y + ad.y));
        float2 hv = *(const float2*)(g_h + (size_t)w * 64 + 2 * lane);
        float ww = (lane < 16) ? w0 : w1;
        accx += ww * hv.x; accy += ww * hv.y;
#pragma unroll
        for (int o = 16; o; o >>= 1) {
            dd0 += __shfl_xor_sync(0xffffffffu, dd0, o);
            dd1 += __shfl_xor_sync(0xffffffffu, dd1, o);
        }
        dd0 += w0; dd1 += w1;
    }

    float inv = (lane < 16) ? (1.f / (dd0 + 1e-16f)) : (1.f / (dd1 + 1e-16f));
    int c0 = 2 * lane, c1 = c0 + 1;
    float o0 = accx * inv + bias[c0];
    float o1 = accy * inv + bias[c1];

    if (LAYER == 1) {
        float sc0 = bgamma[c0] * rsqrtf(bvar[c0] + 1e-5f);
        float sc1 = bgamma[c1] * rsqrtf(bvar[c1] + 1e-5f);
        float y0 = (o0 - bmean[c0]) * sc0 + bbeta[c0];
        float y1 = (o1 - bmean[c1]) * sc1 + bbeta[c1];
        y0 = y0 > 0.f ? y0 : expm1f(y0);
        y1 = y1 > 0.f ? y1 : expm1f(y1);
        *(float2*)(g_x1 + (size_t)w * 64 + c0) = make_float2(y0, y1);
    } else {
        float2* p = (float2*)(g_x1 + (size_t)w * 64 + c0);
        float2 v = *p;
        v.x = fmaxf(v.x, o0);
        v.y = fmaxf(v.y, o1);
        *p = v;
    }
}

// ---------------- launch ----------------
extern "C" void kernel_launch(void* const* d_in, const int* in_sizes, int n_in,
                              void* d_out, int out_size) {
    const float* node_feat = (const float*)d_in[0];
    const int*   ei        = (const int*)  d_in[1];
    const float* W1        = (const float*)d_in[2];
    const float* as1       = (const float*)d_in[3];
    const float* ad1       = (const float*)d_in[4];
    const float* b1        = (const float*)d_in[5];
    const float* bng       = (const float*)d_in[6];
    const float* bnb       = (const float*)d_in[7];
    const float* bnm       = (const float*)d_in[8];
    const float* bnv       = (const float*)d_in[9];
    const float* W2        = (const float*)d_in[10];
    const float* as2       = (const float*)d_in[11];
    const float* ad2       = (const float*)d_in[12];
    const float* b2        = (const float*)d_in[13];
    const float* Wf        = (const float*)d_in[14];
    const float* bf        = (const float*)d_in[15];
    float* out = (float*)d_out;

    float *ph = nullptr, *px1 = nullptr;
    int *pdeg = nullptr;
    cudaGetSymbolAddress((void**)&ph, g_h);
    cudaGetSymbolAddress((void**)&px1, g_x1);
    cudaGetSymbolAddress((void**)&pdeg, g_deg);

    const int eb4 = (EE / 4 + 255) / 256;
    const int nb = (NN + 511) / 512;   // 196 scan blocks
    const int ab = (NN + 7) / 8;       // warp-per-node kernels, 8 warps/block
    const int gb = (NN + 127) / 128;   // gemm64 blocks
    const int fb = (NN + 63) / 64;     // final gemm blocks

    // CSR build (reused by both layers)
    cudaMemsetAsync(pdeg, 0, NN * sizeof(int));
    k_hist<<<eb4, 256>>>(ei);
    k_scanA<<<nb, 512>>>();
    k_scanB<<<1, 256>>>(nb);
    k_scanC<<<nb, 512>>>();
    k_fill<<<eb4, 256>>>(ei);

    // Layer 1: GEMM + fused alphas, then single-pass softmax aggregation
    k_gemm64<128, true><<<gb, 256>>>(node_feat, W1, ph, as1, ad1);
    k_agg<1><<<ab, 256>>>(b1, bng, bnb, bnm, bnv);

    // Layer 2
    k_gemm64<64, true><<<gb, 256>>>(px1, W2, ph, as2, ad2);
    k_agg<2><<<ab, 256>>>(b2, nullptr, nullptr, nullptr, nullptr);

    // Final projection on JK-max output
    k_gemmf<<<fb, 160>>>(px1, Wf, bf, out);
}